// round 15
// baseline (speedup 1.0000x reference)
#include <cuda_runtime.h>
#include <math.h>
#include <stdint.h>

// ---------------- problem constants ----------------
#define BB   8
#define CC   128
#define H0   62
#define W0   62
#define HH   64
#define WW   64
#define HP   66
#define WP   66
#define GG   4
#define PP   9
#define GC   32
#define NPIX (BB*HH*WW)        // 32768
#define OMS  128               // padded om row stride

// ---------------- scratch (device globals) ----------------
__device__ float g_y   [BB*HH*WW*CC];   // conv1x1 output NHWC
__device__ float g_xp  [BB*HP*WP*CC];   // x_proj padded NHWC
__device__ float g_d   [BB*HH*WW*CC];   // dw+LN+GELU NHWC
__device__ float g_om  [NPIX*OMS];      // offsets(72)+logits(36)+pad
__device__ float g_sam [NPIX*CC];       // sampled NHWC
__device__ float g_bt  [4*128*128];     // 4 pre-transposed tf32 B tiles, [k][n]
__device__ float g_bcat[128];           // padded off/mask bias

// ---------------- helpers ----------------
__device__ __forceinline__ float f2tf(float x) {
    uint32_t u;
    asm("cvt.rn.tf32.f32 %0, %1;" : "=r"(u) : "f"(x));
    return __uint_as_float(u);
}
__device__ __forceinline__ void mma_tf32(float c[4], const uint32_t a[4],
                                         uint32_t b0, uint32_t b1) {
    asm volatile(
        "mma.sync.aligned.m16n8k8.row.col.f32.tf32.tf32.f32 "
        "{%0,%1,%2,%3}, {%4,%5,%6,%7}, {%8,%9}, {%0,%1,%2,%3};"
        : "+f"(c[0]), "+f"(c[1]), "+f"(c[2]), "+f"(c[3])
        : "r"(a[0]), "r"(a[1]), "r"(a[2]), "r"(a[3]), "r"(b0), "r"(b1));
}

// ---------------- weight prep ----------------
__global__ void prep_weights_kernel(const float* __restrict__ conv_w,
                                    const float* __restrict__ in_proj_w,
                                    const float* __restrict__ off_w,
                                    const float* __restrict__ mask_w,
                                    const float* __restrict__ off_b,
                                    const float* __restrict__ mask_b,
                                    const float* __restrict__ out_proj_w) {
    int idx = blockIdx.x * blockDim.x + threadIdx.x;
    const int TB = 4 * 128 * 128;
    if (idx < TB) {
        int w = idx >> 14;
        int rem = idx & 16383;
        int k = rem >> 7, n = rem & 127;
        float v;
        if (w == 0)      v = conv_w[n * 128 + k];
        else if (w == 1) v = in_proj_w[k * 128 + n];
        else if (w == 2) v = (n < 72) ? off_w[k * 72 + n]
                           : (n < 108) ? mask_w[k * 36 + (n - 72)] : 0.f;
        else             v = out_proj_w[k * 128 + n];
        g_bt[idx] = f2tf(v);
    } else if (idx < TB + 128) {
        int n = idx - TB;
        g_bcat[n] = (n < 72) ? off_b[n] : (n < 108) ? mask_b[n - 72] : 0.f;
    }
}

// ---------------- zero only the pad ring of g_xp ----------------
__global__ void ring_zero_kernel() {
    int idx = blockIdx.x * blockDim.x + threadIdx.x;
    if (idx >= BB * 260 * 32) return;
    int c4 = (idx & 31) * 4;
    int t = idx >> 5;
    int b = t / 260, p = t % 260;
    int r, cl;
    if (p < 66)       { r = 0;        cl = p; }
    else if (p < 132) { r = 65;       cl = p - 66; }
    else if (p < 196) { r = p - 131;  cl = 0; }
    else              { r = p - 195;  cl = 65; }
    *reinterpret_cast<float4*>(&g_xp[(((size_t)b * HP + r) * WP + cl) * CC + c4]) =
        make_float4(0.f, 0.f, 0.f, 0.f);
}

// ================= shared GEMM machinery (round-8 proven: 512 thr, 16 warps) =========
#define LDA 132
#define SM_A_ELEMS (256 * LDA)
#define SM_B_ELEMS (128 * LDA)
#define SMEM_GEMM ((SM_A_ELEMS + SM_B_ELEMS) * 4)

struct Frag { float acc[4][4][4]; };

__device__ __forceinline__ void mma_stage(float* sA, float* sB, Frag& F,
                                          int wm, int wn, int g, int tig) {
#pragma unroll
    for (int mt = 0; mt < 4; mt++)
#pragma unroll
        for (int nt = 0; nt < 4; nt++)
#pragma unroll
            for (int q = 0; q < 4; q++) F.acc[mt][nt][q] = 0.f;
#pragma unroll
    for (int ks = 0; ks < 16; ks++) {
        int k0 = ks * 8;
        uint32_t af[4][4];
#pragma unroll
        for (int mt = 0; mt < 4; mt++) {
            int rb = wm * 64 + mt * 16 + g;
            af[mt][0] = __float_as_uint(sA[rb * LDA + k0 + tig]);
            af[mt][1] = __float_as_uint(sA[(rb + 8) * LDA + k0 + tig]);
            af[mt][2] = __float_as_uint(sA[rb * LDA + k0 + tig + 4]);
            af[mt][3] = __float_as_uint(sA[(rb + 8) * LDA + k0 + tig + 4]);
        }
#pragma unroll
        for (int nt = 0; nt < 4; nt++) {
            int cb = wn * 32 + nt * 8 + g;
            uint32_t b0 = __float_as_uint(sB[(k0 + tig) * LDA + cb]);
            uint32_t b1 = __float_as_uint(sB[(k0 + tig + 4) * LDA + cb]);
#pragma unroll
            for (int mt = 0; mt < 4; mt++) mma_tf32(F.acc[mt][nt], af[mt], b0, b1);
        }
    }
}

__device__ __forceinline__ void load_B(const float* __restrict__ Bt, float* sB, int tid) {
#pragma unroll
    for (int it = 0; it < 8; it++) {
        int idx = it * 512 + tid;
        int r = idx >> 5, c4 = (idx & 31) * 4;
        *reinterpret_cast<float4*>(&sB[r * LDA + c4]) =
            *reinterpret_cast<const float4*>(&Bt[(size_t)r * 128 + c4]);
    }
}
__device__ __forceinline__ void load_A(const float* __restrict__ A, float* sA,
                                       int m0, int tid) {
#pragma unroll
    for (int it = 0; it < 16; it++) {
        int idx = it * 512 + tid;
        int r = idx >> 5, c4 = (idx & 31) * 4;
        float4 v = *reinterpret_cast<const float4*>(&A[(size_t)(m0 + r) * 128 + c4]);
        v.x = f2tf(v.x); v.y = f2tf(v.y); v.z = f2tf(v.z); v.w = f2tf(v.w);
        *reinterpret_cast<float4*>(&sA[r * LDA + c4]) = v;
    }
}

// ---------------- fused GEMM1+GEMM2 with in-flight NCHW->NHWC transpose ----------------
// CTA = 256 pixels = 4 image rows of one batch. A loaded straight from x:
// task=(ch-quad c, row rr, col j), lane=j -> 4 coalesced LDG.32 + 1 conflict-free STS.128.
__global__ __launch_bounds__(512) void dual_gemm_kernel(
    const float* __restrict__ x,
    const float* __restrict__ Bt1, const float* __restrict__ bias1,
    const float* __restrict__ Bt2, const float* __restrict__ bias2) {
    extern __shared__ float sm[];
    float* sA = sm;
    float* sB = sm + SM_A_ELEMS;
    int tid = threadIdx.x;
    int w = tid >> 5, lane = tid & 31;
    int g = lane >> 2, tig = lane & 3;
    int wm = w >> 2, wn = w & 3;
    int m0 = blockIdx.x * 256;
    int bb = m0 >> 12;
    int r0 = (m0 & 4095) >> 6;

    // A tile: transpose-load from x (zero pad ring), tf32 convert
#pragma unroll 4
    for (int it = 0; it < 16; it++) {
        int task = it * 512 + tid;      // 8192 tasks: c(32) x rr(4) x j(64)
        int j  = task & 63;
        int rr = (task >> 6) & 3;
        int c  = task >> 8;
        int i  = r0 + rr;
        float4 v = make_float4(0.f, 0.f, 0.f, 0.f);
        if ((unsigned)(i - 1) < (unsigned)H0 && (unsigned)(j - 1) < (unsigned)W0) {
            const float* xb = &x[(((size_t)bb * CC + c * 4) * H0 + (i - 1)) * W0 + (j - 1)];
            v.x = xb[0];
            v.y = xb[(size_t)H0 * W0];
            v.z = xb[2 * (size_t)H0 * W0];
            v.w = xb[3 * (size_t)H0 * W0];
        }
        v.x = f2tf(v.x); v.y = f2tf(v.y); v.z = f2tf(v.z); v.w = f2tf(v.w);
        *reinterpret_cast<float4*>(&sA[(rr * 64 + j) * LDA + c * 4]) = v;
    }
    load_B(Bt1, sB, tid);
    __syncthreads();

    Frag F;
    mma_stage(sA, sB, F, wm, wn, g, tig);
    __syncthreads();

#pragma unroll
    for (int mt = 0; mt < 4; mt++) {
        int ml_a = wm * 64 + mt * 16 + g;
        int ml_b = ml_a + 8;
#pragma unroll
        for (int nt = 0; nt < 4; nt++) {
            int cb = wn * 32 + nt * 8 + 2 * tig;
            float bx = __ldg(&bias1[cb]), by = __ldg(&bias1[cb + 1]);
            float ax = F.acc[mt][nt][0] + bx, ay = F.acc[mt][nt][1] + by;
            float bx2 = F.acc[mt][nt][2] + bx, by2 = F.acc[mt][nt][3] + by;
            *reinterpret_cast<float2*>(&g_y[(size_t)(m0 + ml_a) * 128 + cb]) =
                make_float2(ax, ay);
            *reinterpret_cast<float2*>(&g_y[(size_t)(m0 + ml_b) * 128 + cb]) =
                make_float2(bx2, by2);
            sA[ml_a * LDA + cb] = f2tf(ax);
            sA[ml_a * LDA + cb + 1] = f2tf(ay);
            sA[ml_b * LDA + cb] = f2tf(bx2);
            sA[ml_b * LDA + cb + 1] = f2tf(by2);
        }
    }
    load_B(Bt2, sB, tid);
    __syncthreads();

    mma_stage(sA, sB, F, wm, wn, g, tig);

#pragma unroll
    for (int mt = 0; mt < 4; mt++) {
        int m_a = m0 + wm * 64 + mt * 16 + g;
        int m_b = m_a + 8;
        int ba = m_a >> 12, ra = m_a & 4095;
        int bbb = m_b >> 12, rb = m_b & 4095;
        int r1 = ra >> 6, c1 = ra & 63;
        int r2 = rb >> 6, c2 = rb & 63;
        float* da = &g_xp[(((size_t)ba * HP + r1 + 1) * WP + c1 + 1) * CC];
        float* db = &g_xp[(((size_t)bbb * HP + r2 + 1) * WP + c2 + 1) * CC];
#pragma unroll
        for (int nt = 0; nt < 4; nt++) {
            int cb = wn * 32 + nt * 8 + 2 * tig;
            float bx = __ldg(&bias2[cb]), by = __ldg(&bias2[cb + 1]);
            *reinterpret_cast<float2*>(da + cb) =
                make_float2(F.acc[mt][nt][0] + bx, F.acc[mt][nt][1] + by);
            *reinterpret_cast<float2*>(db + cb) =
                make_float2(F.acc[mt][nt][2] + bx, F.acc[mt][nt][3] + by);
        }
    }
}

// ---------------- single GEMM with smem-staged coalesced epilogues ----------------
__global__ __launch_bounds__(512) void mma_gemm_kernel(
    const float* __restrict__ A, const float* __restrict__ Bt,
    const float* __restrict__ bias, float* __restrict__ C, int mode) {
    extern __shared__ float sm[];
    float* sA = sm;
    float* sB = sm + SM_A_ELEMS;
    int tid = threadIdx.x;
    int w = tid >> 5, lane = tid & 31;
    int g = lane >> 2, tig = lane & 3;
    int wm = w >> 2, wn = w & 3;
    int m0 = blockIdx.x * 256;

    load_A(A, sA, m0, tid);
    load_B(Bt, sB, tid);
    __syncthreads();

    Frag F;
    mma_stage(sA, sB, F, wm, wn, g, tig);
    __syncthreads();

    if (mode == 0) {
#pragma unroll
        for (int mt = 0; mt < 4; mt++) {
            int ml = wm * 64 + mt * 16 + g;
#pragma unroll
            for (int nt = 0; nt < 4; nt++) {
                int cb = wn * 32 + nt * 8 + 2 * tig;
                float bx = __ldg(&bias[cb]), by = __ldg(&bias[cb + 1]);
                sA[ml * LDA + cb]           = F.acc[mt][nt][0] + bx;
                sA[ml * LDA + cb + 1]       = F.acc[mt][nt][1] + by;
                sA[(ml + 8) * LDA + cb]     = F.acc[mt][nt][2] + bx;
                sA[(ml + 8) * LDA + cb + 1] = F.acc[mt][nt][3] + by;
            }
        }
        __syncthreads();
#pragma unroll
        for (int it = 0; it < 16; it++) {
            int idx = it * 512 + tid;
            int r = idx >> 5, c4 = (idx & 31) * 4;
            *reinterpret_cast<float4*>(&C[(size_t)(m0 + r) * OMS + c4]) =
                *reinterpret_cast<const float4*>(&sA[r * LDA + c4]);
        }
    } else {
        float* sS = sm;
#pragma unroll
        for (int mt = 0; mt < 4; mt++) {
            int ml = wm * 64 + mt * 16 + g;
#pragma unroll
            for (int nt = 0; nt < 4; nt++) {
                int cb = wn * 32 + nt * 8 + 2 * tig;
                float bx = __ldg(&bias[cb]), by = __ldg(&bias[cb + 1]);
                sS[cb * 260 + ml]           = F.acc[mt][nt][0] + bx;
                sS[(cb + 1) * 260 + ml]     = F.acc[mt][nt][1] + by;
                sS[cb * 260 + ml + 8]       = F.acc[mt][nt][2] + bx;
                sS[(cb + 1) * 260 + ml + 8] = F.acc[mt][nt][3] + by;
            }
        }
        __syncthreads();
        int b = m0 >> 12, rem0 = m0 & 4095;
#pragma unroll
        for (int it = 0; it < 16; it++) {
            int idx = it * 512 + tid;
            int c = idx >> 6, p4 = (idx & 63) * 4;
            *reinterpret_cast<float4*>(&C[((size_t)b * CC + c) * 4096 + rem0 + p4]) =
                *reinterpret_cast<const float4*>(&sS[c * 260 + p4]);
        }
    }
}

// ---------------- dw3x3 + LN + GELU, horizontal-reuse (round-8 verbatim) ----------------
__global__ __launch_bounds__(256) void dw_ln_gelu_kernel(
    const float* __restrict__ dw_w, const float* __restrict__ dw_b,
    const float* __restrict__ ln_g, const float* __restrict__ ln_b) {
    __shared__ float dws[CC * 9];
    int tid = threadIdx.x;
    for (int t = tid; t < CC * 9; t += 256) dws[t] = dw_w[t];
    __syncthreads();

    int warp = tid >> 5, lane = tid & 31;
    int bi = blockIdx.x;
    int b = bi >> 6, i = bi & 63;
    int j0 = warp * 8;
    int c4 = lane * 4;

    float wgt[4][9];
#pragma unroll
    for (int q = 0; q < 4; q++)
#pragma unroll
        for (int t = 0; t < 9; t++) wgt[q][t] = dws[(c4 + q) * 9 + t];

    float4 db = *reinterpret_cast<const float4*>(&dw_b[c4]);
    float v[8][4];
#pragma unroll
    for (int p = 0; p < 8; p++) {
        v[p][0] = db.x; v[p][1] = db.y; v[p][2] = db.z; v[p][3] = db.w;
    }

    bool y0ok = (i >= 1), y2ok = (i <= 62);
    const float* rowm = &g_y[((size_t)(b * HH + i - 1) * WW) * CC + c4];
    const float* row0 = &g_y[((size_t)(b * HH + i    ) * WW) * CC + c4];
    const float* rowp = &g_y[((size_t)(b * HH + i + 1) * WW) * CC + c4];

#pragma unroll
    for (int jj = 0; jj < 10; jj++) {
        int xx = j0 + jj - 1;
        float4 r0 = make_float4(0.f, 0.f, 0.f, 0.f);
        float4 r1 = r0, r2 = r0;
        if ((unsigned)xx < (unsigned)WW) {
            if (y0ok) r0 = *reinterpret_cast<const float4*>(rowm + (size_t)xx * CC);
            r1 = *reinterpret_cast<const float4*>(row0 + (size_t)xx * CC);
            if (y2ok) r2 = *reinterpret_cast<const float4*>(rowp + (size_t)xx * CC);
        }
        float rq[3][4] = {{r0.x, r0.y, r0.z, r0.w},
                          {r1.x, r1.y, r1.z, r1.w},
                          {r2.x, r2.y, r2.z, r2.w}};
#pragma unroll
        for (int p = 0; p < 8; p++) {
            int kx = jj - p;
            if (kx >= 0 && kx <= 2) {
#pragma unroll
                for (int ky = 0; ky < 3; ky++)
#pragma unroll
                    for (int q = 0; q < 4; q++)
                        v[p][q] += rq[ky][q] * wgt[q][ky * 3 + kx];
            }
        }
    }

    float4 lg = *reinterpret_cast<const float4*>(&ln_g[c4]);
    float4 lb = *reinterpret_cast<const float4*>(&ln_b[c4]);
    float gv[4] = {lg.x, lg.y, lg.z, lg.w};
    float bv[4] = {lb.x, lb.y, lb.z, lb.w};

#pragma unroll
    for (int p = 0; p < 8; p++) {
        float s = v[p][0] + v[p][1] + v[p][2] + v[p][3];
#pragma unroll
        for (int o = 16; o; o >>= 1) s += __shfl_xor_sync(0xffffffffu, s, o);
        float mu = s * (1.f / 128.f);
        float d2 = 0.f;
#pragma unroll
        for (int q = 0; q < 4; q++) { float t = v[p][q] - mu; d2 += t * t; }
#pragma unroll
        for (int o = 16; o; o >>= 1) d2 += __shfl_xor_sync(0xffffffffu, d2, o);
        float inv = rsqrtf(d2 * (1.f / 128.f) + 1e-5f);
        float4 outv;
        float* op = reinterpret_cast<float*>(&outv);
#pragma unroll
        for (int q = 0; q < 4; q++) {
            float t = (v[p][q] - mu) * inv * gv[q] + bv[q];
            op[q] = 0.5f * t * (1.f + erff(t * 0.70710678118654752440f));
        }
        int pix = (b << 12) + (i << 6) + j0 + p;
        *reinterpret_cast<float4*>(&g_d[(size_t)pix * CC + c4]) = outv;
    }
}

// ---------------- DCNv3 core: smem-windowed softmax + bilinear sampling ----------------
__global__ __launch_bounds__(512) void sample_kernel() {
    __shared__ float win[16 * 16 * 32];   // 32 KB
    int blk = blockIdx.x;                 // b*256 + tile*4 + g
    int g = blk & 3;
    int tile = (blk >> 2) & 63;
    int b = blk >> 8;
    int i0 = (tile >> 3) * 8, j0 = (tile & 7) * 8;
    int w = threadIdx.x >> 5, lane = threadIdx.x & 31;
    int cbase = g * GC + lane;
    const float* xpb = g_xp + (size_t)b * (HP * WP * CC);

#pragma unroll
    for (int t = 0; t < 16; t++) {
        int pos = t * 16 + w;
        int r = pos >> 4, cl = pos & 15;
        int y = i0 - 3 + r, x = j0 - 3 + cl;
        float v = 0.f;
        if ((unsigned)y < (unsigned)HP && (unsigned)x < (unsigned)WP)
            v = xpb[(y * WP + x) * CC + cbase];
        win[pos * 32 + lane] = v;
    }
    __syncthreads();

#pragma unroll 1
    for (int q = 0; q < 4; q++) {
        int pl = w * 4 + q;
        int i = i0 + (pl >> 3), j = j0 + (pl & 7);
        int pix = (b << 12) + (i << 6) + j;
        const float* omr = g_om + (size_t)pix * OMS;

        float lg[9];
        float mx = -1e30f;
#pragma unroll
        for (int p = 0; p < 9; p++) { lg[p] = omr[72 + g * 9 + p]; mx = fmaxf(mx, lg[p]); }
        float sum = 0.f;
#pragma unroll
        for (int p = 0; p < 9; p++) { lg[p] = expf(lg[p] - mx); sum += lg[p]; }
        float minv = 1.f / sum;

        float acc = 0.f;
#pragma unroll
        for (int p = 0; p < 9; p++) {
            float offx = omr[(g * 9 + p) * 2 + 0];
            float offy = omr[(g * 9 + p) * 2 + 1];
            float ix = (float)(j + p / 3) + offx;
            float iy = (float)(i + (p - (p / 3) * 3)) + offy;
            float x0f = floorf(ix), y0f = floorf(iy);
            float wx1 = ix - x0f, wy1 = iy - y0f;
            float wx0 = 1.f - wx1, wy0 = 1.f - wy1;
            int x0 = (int)x0f, y0 = (int)y0f;
            float v00, v10, v01, v11;
            int sx = x0 - (j0 - 3), sy = y0 - (i0 - 3);
            if (sx >= 0 && sx <= 14 && sy >= 0 && sy <= 14) {
                int base = (sy * 16 + sx) * 32 + lane;
                v00 = win[base];
                v10 = win[base + 32];
                v01 = win[base + 16 * 32];
                v11 = win[base + 16 * 32 + 32];
            } else {
                v00 = v10 = v01 = v11 = 0.f;
                bool xv0 = (x0 >= 0) & (x0 < WP);
                bool xv1 = (x0 + 1 >= 0) & (x0 + 1 < WP);
                bool yv0 = (y0 >= 0) & (y0 < HP);
                bool yv1 = (y0 + 1 >= 0) & (y0 + 1 < HP);
                if (yv0) {
                    if (xv0) v00 = xpb[(y0 * WP + x0) * CC + cbase];
                    if (xv1) v10 = xpb[(y0 * WP + x0 + 1) * CC + cbase];
                }
                if (yv1) {
                    if (xv0) v01 = xpb[((y0 + 1) * WP + x0) * CC + cbase];
                    if (xv1) v11 = xpb[((y0 + 1) * WP + x0 + 1) * CC + cbase];
                }
            }
            float bi = (v00 * wx0 + v10 * wx1) * wy0 + (v01 * wx0 + v11 * wx1) * wy1;
            acc += (lg[p] * minv) * bi;
        }
        g_sam[(size_t)pix * CC + cbase] = acc;
    }
}

// ---------------- launch ----------------
extern "C" void kernel_launch(void* const* d_in, const int* in_sizes, int n_in,
                              void* d_out, int out_size) {
    const float* x          = (const float*)d_in[0];
    const float* conv_w     = (const float*)d_in[1];
    const float* conv_b     = (const float*)d_in[2];
    const float* in_proj_w  = (const float*)d_in[3];
    const float* in_proj_b  = (const float*)d_in[4];
    const float* dw_w       = (const float*)d_in[5];
    const float* dw_b       = (const float*)d_in[6];
    const float* ln_g       = (const float*)d_in[7];
    const float* ln_b       = (const float*)d_in[8];
    const float* off_w      = (const float*)d_in[9];
    const float* off_b      = (const float*)d_in[10];
    const float* mask_w     = (const float*)d_in[11];
    const float* mask_b     = (const float*)d_in[12];
    const float* out_proj_w = (const float*)d_in[13];
    const float* out_proj_b = (const float*)d_in[14];
    float* out = (float*)d_out;

    float *p_d, *p_om, *p_sam, *p_bt, *p_bcat;
    cudaGetSymbolAddress((void**)&p_d,    g_d);
    cudaGetSymbolAddress((void**)&p_om,   g_om);
    cudaGetSymbolAddress((void**)&p_sam,  g_sam);
    cudaGetSymbolAddress((void**)&p_bt,   g_bt);
    cudaGetSymbolAddress((void**)&p_bcat, g_bcat);

    cudaFuncSetAttribute(dual_gemm_kernel,
                         cudaFuncAttributeMaxDynamicSharedMemorySize, SMEM_GEMM);
    cudaFuncSetAttribute(mma_gemm_kernel,
                         cudaFuncAttributeMaxDynamicSharedMemorySize, SMEM_GEMM);

    // 1. zero pad ring of g_xp
    ring_zero_kernel<<<(BB * 260 * 32 + 255) / 256, 256>>>();
    // 2. weight prep
    prep_weights_kernel<<<(4 * 16384 + 128 + 255) / 256, 256>>>(
        conv_w, in_proj_w, off_w, mask_w, off_b, mask_b, out_proj_w);
    // 3. fused GEMM1+GEMM2 with in-flight NCHW->NHWC transpose
    dual_gemm_kernel<<<NPIX / 256, 512, SMEM_GEMM>>>(
        x, p_bt + 0 * 16384, conv_b, p_bt + 1 * 16384, in_proj_b);
    // 4. depthwise + LN + GELU (horizontal-reuse)
    dw_ln_gelu_kernel<<<BB * HH, 256>>>(dw_w, dw_b, ln_g, ln_b);
    // 5. GEMM3: [offset|logits|pad] = d @ wcat + bcat (coalesced rows)
    mma_gemm_kernel<<<NPIX / 256, 512, SMEM_GEMM>>>(p_d, p_bt + 2 * 16384, p_bcat, p_om, 0);
    // 6. softmax + bilinear sampling (smem-windowed 8x8 tiles x group)
    sample_kernel<<<BB * 64 * GG, 512>>>();
    // 7. GEMM4: out = sampled @ out_proj_w + b, NCHW via smem transpose
    mma_gemm_kernel<<<NPIX / 256, 512, SMEM_GEMM>>>(p_sam, p_bt + 3 * 16384, out_proj_b, out, 2);
}

// round 17
// speedup vs baseline: 1.4251x; 1.4251x over previous
#include <cuda_runtime.h>
#include <math.h>
#include <stdint.h>

// ---------------- problem constants ----------------
#define BB   8
#define CC   128
#define H0   62
#define W0   62
#define HH   64
#define WW   64
#define HP   66
#define WP   66
#define GG   4
#define PP   9
#define GC   32
#define NPIX (BB*HH*WW)        // 32768
#define OMS  128               // padded om row stride

// ---------------- scratch (device globals) ----------------
__device__ float g_xpad[BB*HH*WW*CC];   // x in NHWC, zero ring
__device__ float g_y   [BB*HH*WW*CC];   // conv1x1 output NHWC
__device__ float g_xp  [BB*HP*WP*CC];   // x_proj padded NHWC
__device__ float g_d   [BB*HH*WW*CC];   // dw+LN+GELU NHWC
__device__ float g_om  [NPIX*OMS];      // offsets(72)+logits(36)+pad
__device__ float g_sam [NPIX*CC];       // sampled NHWC
__device__ float g_bt  [4*128*128];     // 4 pre-transposed tf32 B tiles, [k][n]
__device__ float g_bcat[128];           // padded off/mask bias

// ---------------- helpers ----------------
__device__ __forceinline__ float f2tf(float x) {
    uint32_t u;
    asm("cvt.rn.tf32.f32 %0, %1;" : "=r"(u) : "f"(x));
    return __uint_as_float(u);
}
__device__ __forceinline__ void mma_tf32(float c[4], const uint32_t a[4],
                                         uint32_t b0, uint32_t b1) {
    asm volatile(
        "mma.sync.aligned.m16n8k8.row.col.f32.tf32.tf32.f32 "
        "{%0,%1,%2,%3}, {%4,%5,%6,%7}, {%8,%9}, {%0,%1,%2,%3};"
        : "+f"(c[0]), "+f"(c[1]), "+f"(c[2]), "+f"(c[3])
        : "r"(a[0]), "r"(a[1]), "r"(a[2]), "r"(a[3]), "r"(b0), "r"(b1));
}

// ---------------- weight prep ----------------
__global__ void prep_weights_kernel(const float* __restrict__ conv_w,
                                    const float* __restrict__ in_proj_w,
                                    const float* __restrict__ off_w,
                                    const float* __restrict__ mask_w,
                                    const float* __restrict__ off_b,
                                    const float* __restrict__ mask_b,
                                    const float* __restrict__ out_proj_w) {
    int idx = blockIdx.x * blockDim.x + threadIdx.x;
    const int TB = 4 * 128 * 128;
    if (idx < TB) {
        int w = idx >> 14;
        int rem = idx & 16383;
        int k = rem >> 7, n = rem & 127;
        float v;
        if (w == 0)      v = conv_w[n * 128 + k];
        else if (w == 1) v = in_proj_w[k * 128 + n];
        else if (w == 2) v = (n < 72) ? off_w[k * 72 + n]
                           : (n < 108) ? mask_w[k * 36 + (n - 72)] : 0.f;
        else             v = out_proj_w[k * 128 + n];
        g_bt[idx] = f2tf(v);
    } else if (idx < TB + 128) {
        int n = idx - TB;
        g_bcat[n] = (n < 72) ? off_b[n] : (n < 108) ? mask_b[n - 72] : 0.f;
    }
}

// ---------------- zero only the pad ring of g_xp ----------------
__global__ void ring_zero_kernel() {
    int idx = blockIdx.x * blockDim.x + threadIdx.x;
    if (idx >= BB * 260 * 32) return;
    int c4 = (idx & 31) * 4;
    int t = idx >> 5;
    int b = t / 260, p = t % 260;
    int r, cl;
    if (p < 66)       { r = 0;        cl = p; }
    else if (p < 132) { r = 65;       cl = p - 66; }
    else if (p < 196) { r = p - 131;  cl = 0; }
    else              { r = p - 195;  cl = 65; }
    *reinterpret_cast<float4*>(&g_xp[(((size_t)b * HP + r) * WP + cl) * CC + c4]) =
        make_float4(0.f, 0.f, 0.f, 0.f);
}

// ---------------- NCHW -> NHWC transpose with zero pad ring ----------------
__global__ void transpose_pad_kernel(const float* __restrict__ x) {
    __shared__ float s[32][33];
    int bi = blockIdx.x;
    int b = bi >> 6, i = bi & 63;
    int j0 = blockIdx.y * 32, c0 = blockIdx.z * 32;
    int tx = threadIdx.x, ty = threadIdx.y;
    int j = j0 + tx;
    float v = 0.f;
    if (i >= 1 && i <= 62 && j >= 1 && j <= 62)
        v = x[((b * CC + c0 + ty) * H0 + (i - 1)) * W0 + (j - 1)];
    s[ty][tx] = v;
    __syncthreads();
    int jw = j0 + ty;
    g_xpad[((b * HH + i) * WW + jw) * CC + c0 + tx] = s[tx][ty];
}

// ================= shared GEMM machinery (round-8 proven: 512 thr, 16 warps) =========
#define LDA 132
#define SM_A_ELEMS (256 * LDA)
#define SM_B_ELEMS (128 * LDA)
#define SMEM_GEMM ((SM_A_ELEMS + SM_B_ELEMS) * 4)

struct Frag { float acc[4][4][4]; };

__device__ __forceinline__ void mma_stage(float* sA, float* sB, Frag& F,
                                          int wm, int wn, int g, int tig) {
#pragma unroll
    for (int mt = 0; mt < 4; mt++)
#pragma unroll
        for (int nt = 0; nt < 4; nt++)
#pragma unroll
            for (int q = 0; q < 4; q++) F.acc[mt][nt][q] = 0.f;
#pragma unroll
    for (int ks = 0; ks < 16; ks++) {
        int k0 = ks * 8;
        uint32_t af[4][4];
#pragma unroll
        for (int mt = 0; mt < 4; mt++) {
            int rb = wm * 64 + mt * 16 + g;
            af[mt][0] = __float_as_uint(sA[rb * LDA + k0 + tig]);
            af[mt][1] = __float_as_uint(sA[(rb + 8) * LDA + k0 + tig]);
            af[mt][2] = __float_as_uint(sA[rb * LDA + k0 + tig + 4]);
            af[mt][3] = __float_as_uint(sA[(rb + 8) * LDA + k0 + tig + 4]);
        }
#pragma unroll
        for (int nt = 0; nt < 4; nt++) {
            int cb = wn * 32 + nt * 8 + g;
            uint32_t b0 = __float_as_uint(sB[(k0 + tig) * LDA + cb]);
            uint32_t b1 = __float_as_uint(sB[(k0 + tig + 4) * LDA + cb]);
#pragma unroll
            for (int mt = 0; mt < 4; mt++) mma_tf32(F.acc[mt][nt], af[mt], b0, b1);
        }
    }
}

__device__ __forceinline__ void load_B(const float* __restrict__ Bt, float* sB, int tid) {
#pragma unroll
    for (int it = 0; it < 8; it++) {
        int idx = it * 512 + tid;
        int r = idx >> 5, c4 = (idx & 31) * 4;
        *reinterpret_cast<float4*>(&sB[r * LDA + c4]) =
            *reinterpret_cast<const float4*>(&Bt[(size_t)r * 128 + c4]);
    }
}
__device__ __forceinline__ void load_A(const float* __restrict__ A, float* sA,
                                       int m0, int tid) {
#pragma unroll
    for (int it = 0; it < 16; it++) {
        int idx = it * 512 + tid;
        int r = idx >> 5, c4 = (idx & 31) * 4;
        float4 v = *reinterpret_cast<const float4*>(&A[(size_t)(m0 + r) * 128 + c4]);
        v.x = f2tf(v.x); v.y = f2tf(v.y); v.z = f2tf(v.z); v.w = f2tf(v.w);
        *reinterpret_cast<float4*>(&sA[r * LDA + c4]) = v;
    }
}

// ---------------- fused GEMM1+GEMM2 (round-14 verbatim: reads g_xpad) ----------------
__global__ __launch_bounds__(512) void dual_gemm_kernel(
    const float* __restrict__ Bt1, const float* __restrict__ bias1,
    const float* __restrict__ Bt2, const float* __restrict__ bias2) {
    extern __shared__ float sm[];
    float* sA = sm;
    float* sB = sm + SM_A_ELEMS;
    int tid = threadIdx.x;
    int w = tid >> 5, lane = tid & 31;
    int g = lane >> 2, tig = lane & 3;
    int wm = w >> 2, wn = w & 3;
    int m0 = blockIdx.x * 256;

    load_A(g_xpad, sA, m0, tid);
    load_B(Bt1, sB, tid);
    __syncthreads();

    Frag F;
    mma_stage(sA, sB, F, wm, wn, g, tig);
    __syncthreads();

#pragma unroll
    for (int mt = 0; mt < 4; mt++) {
        int ml_a = wm * 64 + mt * 16 + g;
        int ml_b = ml_a + 8;
#pragma unroll
        for (int nt = 0; nt < 4; nt++) {
            int cb = wn * 32 + nt * 8 + 2 * tig;
            float bx = __ldg(&bias1[cb]), by = __ldg(&bias1[cb + 1]);
            float ax = F.acc[mt][nt][0] + bx, ay = F.acc[mt][nt][1] + by;
            float bx2 = F.acc[mt][nt][2] + bx, by2 = F.acc[mt][nt][3] + by;
            *reinterpret_cast<float2*>(&g_y[(size_t)(m0 + ml_a) * 128 + cb]) =
                make_float2(ax, ay);
            *reinterpret_cast<float2*>(&g_y[(size_t)(m0 + ml_b) * 128 + cb]) =
                make_float2(bx2, by2);
            sA[ml_a * LDA + cb] = f2tf(ax);
            sA[ml_a * LDA + cb + 1] = f2tf(ay);
            sA[ml_b * LDA + cb] = f2tf(bx2);
            sA[ml_b * LDA + cb + 1] = f2tf(by2);
        }
    }
    load_B(Bt2, sB, tid);
    __syncthreads();

    mma_stage(sA, sB, F, wm, wn, g, tig);

#pragma unroll
    for (int mt = 0; mt < 4; mt++) {
        int m_a = m0 + wm * 64 + mt * 16 + g;
        int m_b = m_a + 8;
        int ba = m_a >> 12, ra = m_a & 4095;
        int bb = m_b >> 12, rb = m_b & 4095;
        int r1 = ra >> 6, c1 = ra & 63;
        int r2 = rb >> 6, c2 = rb & 63;
        float* da = &g_xp[(((size_t)ba * HP + r1 + 1) * WP + c1 + 1) * CC];
        float* db = &g_xp[(((size_t)bb * HP + r2 + 1) * WP + c2 + 1) * CC];
#pragma unroll
        for (int nt = 0; nt < 4; nt++) {
            int cb = wn * 32 + nt * 8 + 2 * tig;
            float bx = __ldg(&bias2[cb]), by = __ldg(&bias2[cb + 1]);
            *reinterpret_cast<float2*>(da + cb) =
                make_float2(F.acc[mt][nt][0] + bx, F.acc[mt][nt][1] + by);
            *reinterpret_cast<float2*>(db + cb) =
                make_float2(F.acc[mt][nt][2] + bx, F.acc[mt][nt][3] + by);
        }
    }
}

// ---------------- single GEMM with smem-staged coalesced epilogues ----------------
__global__ __launch_bounds__(512) void mma_gemm_kernel(
    const float* __restrict__ A, const float* __restrict__ Bt,
    const float* __restrict__ bias, float* __restrict__ C, int mode) {
    extern __shared__ float sm[];
    float* sA = sm;
    float* sB = sm + SM_A_ELEMS;
    int tid = threadIdx.x;
    int w = tid >> 5, lane = tid & 31;
    int g = lane >> 2, tig = lane & 3;
    int wm = w >> 2, wn = w & 3;
    int m0 = blockIdx.x * 256;

    load_A(A, sA, m0, tid);
    load_B(Bt, sB, tid);
    __syncthreads();

    Frag F;
    mma_stage(sA, sB, F, wm, wn, g, tig);
    __syncthreads();

    if (mode == 0) {
#pragma unroll
        for (int mt = 0; mt < 4; mt++) {
            int ml = wm * 64 + mt * 16 + g;
#pragma unroll
            for (int nt = 0; nt < 4; nt++) {
                int cb = wn * 32 + nt * 8 + 2 * tig;
                float bx = __ldg(&bias[cb]), by = __ldg(&bias[cb + 1]);
                sA[ml * LDA + cb]           = F.acc[mt][nt][0] + bx;
                sA[ml * LDA + cb + 1]       = F.acc[mt][nt][1] + by;
                sA[(ml + 8) * LDA + cb]     = F.acc[mt][nt][2] + bx;
                sA[(ml + 8) * LDA + cb + 1] = F.acc[mt][nt][3] + by;
            }
        }
        __syncthreads();
#pragma unroll
        for (int it = 0; it < 16; it++) {
            int idx = it * 512 + tid;
            int r = idx >> 5, c4 = (idx & 31) * 4;
            *reinterpret_cast<float4*>(&C[(size_t)(m0 + r) * OMS + c4]) =
                *reinterpret_cast<const float4*>(&sA[r * LDA + c4]);
        }
    } else {
        float* sS = sm;
#pragma unroll
        for (int mt = 0; mt < 4; mt++) {
            int ml = wm * 64 + mt * 16 + g;
#pragma unroll
            for (int nt = 0; nt < 4; nt++) {
                int cb = wn * 32 + nt * 8 + 2 * tig;
                float bx = __ldg(&bias[cb]), by = __ldg(&bias[cb + 1]);
                sS[cb * 260 + ml]           = F.acc[mt][nt][0] + bx;
                sS[(cb + 1) * 260 + ml]     = F.acc[mt][nt][1] + by;
                sS[cb * 260 + ml + 8]       = F.acc[mt][nt][2] + bx;
                sS[(cb + 1) * 260 + ml + 8] = F.acc[mt][nt][3] + by;
            }
        }
        __syncthreads();
        int b = m0 >> 12, rem0 = m0 & 4095;
#pragma unroll
        for (int it = 0; it < 16; it++) {
            int idx = it * 512 + tid;
            int c = idx >> 6, p4 = (idx & 63) * 4;
            *reinterpret_cast<float4*>(&C[((size_t)b * CC + c) * 4096 + rem0 + p4]) =
                *reinterpret_cast<const float4*>(&sS[c * 260 + p4]);
        }
    }
}

// ---------------- dw3x3 + LN + GELU: 4 pixels/warp, >=3 CTAs/SM ----------------
// grid = BB*HH*2 = 1024; block 256 = 8 warps; warp = 4-pixel horizontal run.
// Window 3 rows x 6 cols loaded once; accumulation order per pixel identical to
// the 8-pixel version (jj ascending -> kx ascending) => bit-identical output.
__global__ __launch_bounds__(256, 3) void dw_ln_gelu_kernel(
    const float* __restrict__ dw_w, const float* __restrict__ dw_b,
    const float* __restrict__ ln_g, const float* __restrict__ ln_b) {
    __shared__ float dws[CC * 9];
    int tid = threadIdx.x;
    for (int t = tid; t < CC * 9; t += 256) dws[t] = dw_w[t];
    __syncthreads();

    int warp = tid >> 5, lane = tid & 31;
    int bi = blockIdx.x;                 // b*128 + i*2 + half
    int b = bi >> 7;
    int rem = bi & 127;
    int i = rem >> 1;
    int j0 = (rem & 1) * 32 + warp * 4;
    int c4 = lane * 4;

    float wgt[4][9];
#pragma unroll
    for (int q = 0; q < 4; q++)
#pragma unroll
        for (int t = 0; t < 9; t++) wgt[q][t] = dws[(c4 + q) * 9 + t];

    float4 db = *reinterpret_cast<const float4*>(&dw_b[c4]);
    float v[4][4];
#pragma unroll
    for (int p = 0; p < 4; p++) {
        v[p][0] = db.x; v[p][1] = db.y; v[p][2] = db.z; v[p][3] = db.w;
    }

    bool y0ok = (i >= 1), y2ok = (i <= 62);
    const float* rowm = &g_y[((size_t)(b * HH + i - 1) * WW) * CC + c4];
    const float* row0 = &g_y[((size_t)(b * HH + i    ) * WW) * CC + c4];
    const float* rowp = &g_y[((size_t)(b * HH + i + 1) * WW) * CC + c4];

#pragma unroll
    for (int jj = 0; jj < 6; jj++) {
        int xx = j0 + jj - 1;
        float4 r0 = make_float4(0.f, 0.f, 0.f, 0.f);
        float4 r1 = r0, r2 = r0;
        if ((unsigned)xx < (unsigned)WW) {
            if (y0ok) r0 = *reinterpret_cast<const float4*>(rowm + (size_t)xx * CC);
            r1 = *reinterpret_cast<const float4*>(row0 + (size_t)xx * CC);
            if (y2ok) r2 = *reinterpret_cast<const float4*>(rowp + (size_t)xx * CC);
        }
        float rq[3][4] = {{r0.x, r0.y, r0.z, r0.w},
                          {r1.x, r1.y, r1.z, r1.w},
                          {r2.x, r2.y, r2.z, r2.w}};
#pragma unroll
        for (int p = 0; p < 4; p++) {
            int kx = jj - p;
            if (kx >= 0 && kx <= 2) {
#pragma unroll
                for (int ky = 0; ky < 3; ky++)
#pragma unroll
                    for (int q = 0; q < 4; q++)
                        v[p][q] += rq[ky][q] * wgt[q][ky * 3 + kx];
            }
        }
    }

    float4 lg = *reinterpret_cast<const float4*>(&ln_g[c4]);
    float4 lb = *reinterpret_cast<const float4*>(&ln_b[c4]);
    float gv[4] = {lg.x, lg.y, lg.z, lg.w};
    float bv[4] = {lb.x, lb.y, lb.z, lb.w};

#pragma unroll
    for (int p = 0; p < 4; p++) {
        float s = v[p][0] + v[p][1] + v[p][2] + v[p][3];
#pragma unroll
        for (int o = 16; o; o >>= 1) s += __shfl_xor_sync(0xffffffffu, s, o);
        float mu = s * (1.f / 128.f);
        float d2 = 0.f;
#pragma unroll
        for (int q = 0; q < 4; q++) { float t = v[p][q] - mu; d2 += t * t; }
#pragma unroll
        for (int o = 16; o; o >>= 1) d2 += __shfl_xor_sync(0xffffffffu, d2, o);
        float inv = rsqrtf(d2 * (1.f / 128.f) + 1e-5f);
        float4 outv;
        float* op = reinterpret_cast<float*>(&outv);
#pragma unroll
        for (int q = 0; q < 4; q++) {
            float t = (v[p][q] - mu) * inv * gv[q] + bv[q];
            op[q] = 0.5f * t * (1.f + erff(t * 0.70710678118654752440f));
        }
        int pix = (b << 12) + (i << 6) + j0 + p;
        *reinterpret_cast<float4*>(&g_d[(size_t)pix * CC + c4]) = outv;
    }
}

// ---------------- DCNv3 core: smem-windowed softmax + bilinear sampling ----------------
__global__ __launch_bounds__(512) void sample_kernel() {
    __shared__ float win[16 * 16 * 32];   // 32 KB
    int blk = blockIdx.x;                 // b*256 + tile*4 + g
    int g = blk & 3;
    int tile = (blk >> 2) & 63;
    int b = blk >> 8;
    int i0 = (tile >> 3) * 8, j0 = (tile & 7) * 8;
    int w = threadIdx.x >> 5, lane = threadIdx.x & 31;
    int cbase = g * GC + lane;
    const float* xpb = g_xp + (size_t)b * (HP * WP * CC);

#pragma unroll
    for (int t = 0; t < 16; t++) {
        int pos = t * 16 + w;
        int r = pos >> 4, cl = pos & 15;
        int y = i0 - 3 + r, x = j0 - 3 + cl;
        float v = 0.f;
        if ((unsigned)y < (unsigned)HP && (unsigned)x < (unsigned)WP)
            v = xpb[(y * WP + x) * CC + cbase];
        win[pos * 32 + lane] = v;
    }
    __syncthreads();

#pragma unroll 1
    for (int q = 0; q < 4; q++) {
        int pl = w * 4 + q;
        int i = i0 + (pl >> 3), j = j0 + (pl & 7);
        int pix = (b << 12) + (i << 6) + j;
        const float* omr = g_om + (size_t)pix * OMS;

        float lg[9];
        float mx = -1e30f;
#pragma unroll
        for (int p = 0; p < 9; p++) { lg[p] = omr[72 + g * 9 + p]; mx = fmaxf(mx, lg[p]); }
        float sum = 0.f;
#pragma unroll
        for (int p = 0; p < 9; p++) { lg[p] = expf(lg[p] - mx); sum += lg[p]; }
        float minv = 1.f / sum;

        float acc = 0.f;
#pragma unroll
        for (int p = 0; p < 9; p++) {
            float offx = omr[(g * 9 + p) * 2 + 0];
            float offy = omr[(g * 9 + p) * 2 + 1];
            float ix = (float)(j + p / 3) + offx;
            float iy = (float)(i + (p - (p / 3) * 3)) + offy;
            float x0f = floorf(ix), y0f = floorf(iy);
            float wx1 = ix - x0f, wy1 = iy - y0f;
            float wx0 = 1.f - wx1, wy0 = 1.f - wy1;
            int x0 = (int)x0f, y0 = (int)y0f;
            float v00, v10, v01, v11;
            int sx = x0 - (j0 - 3), sy = y0 - (i0 - 3);
            if (sx >= 0 && sx <= 14 && sy >= 0 && sy <= 14) {
                int base = (sy * 16 + sx) * 32 + lane;
                v00 = win[base];
                v10 = win[base + 32];
                v01 = win[base + 16 * 32];
                v11 = win[base + 16 * 32 + 32];
            } else {
                v00 = v10 = v01 = v11 = 0.f;
                bool xv0 = (x0 >= 0) & (x0 < WP);
                bool xv1 = (x0 + 1 >= 0) & (x0 + 1 < WP);
                bool yv0 = (y0 >= 0) & (y0 < HP);
                bool yv1 = (y0 + 1 >= 0) & (y0 + 1 < HP);
                if (yv0) {
                    if (xv0) v00 = xpb[(y0 * WP + x0) * CC + cbase];
                    if (xv1) v10 = xpb[(y0 * WP + x0 + 1) * CC + cbase];
                }
                if (yv1) {
                    if (xv0) v01 = xpb[((y0 + 1) * WP + x0) * CC + cbase];
                    if (xv1) v11 = xpb[((y0 + 1) * WP + x0 + 1) * CC + cbase];
                }
            }
            float bi = (v00 * wx0 + v10 * wx1) * wy0 + (v01 * wx0 + v11 * wx1) * wy1;
            acc += (lg[p] * minv) * bi;
        }
        g_sam[(size_t)pix * CC + cbase] = acc;
    }
}

// ---------------- launch ----------------
extern "C" void kernel_launch(void* const* d_in, const int* in_sizes, int n_in,
                              void* d_out, int out_size) {
    const float* x          = (const float*)d_in[0];
    const float* conv_w     = (const float*)d_in[1];
    const float* conv_b     = (const float*)d_in[2];
    const float* in_proj_w  = (const float*)d_in[3];
    const float* in_proj_b  = (const float*)d_in[4];
    const float* dw_w       = (const float*)d_in[5];
    const float* dw_b       = (const float*)d_in[6];
    const float* ln_g       = (const float*)d_in[7];
    const float* ln_b       = (const float*)d_in[8];
    const float* off_w      = (const float*)d_in[9];
    const float* off_b      = (const float*)d_in[10];
    const float* mask_w     = (const float*)d_in[11];
    const float* mask_b     = (const float*)d_in[12];
    const float* out_proj_w = (const float*)d_in[13];
    const float* out_proj_b = (const float*)d_in[14];
    float* out = (float*)d_out;

    float *p_d, *p_om, *p_sam, *p_bt, *p_bcat;
    cudaGetSymbolAddress((void**)&p_d,    g_d);
    cudaGetSymbolAddress((void**)&p_om,   g_om);
    cudaGetSymbolAddress((void**)&p_sam,  g_sam);
    cudaGetSymbolAddress((void**)&p_bt,   g_bt);
    cudaGetSymbolAddress((void**)&p_bcat, g_bcat);

    cudaFuncSetAttribute(dual_gemm_kernel,
                         cudaFuncAttributeMaxDynamicSharedMemorySize, SMEM_GEMM);
    cudaFuncSetAttribute(mma_gemm_kernel,
                         cudaFuncAttributeMaxDynamicSharedMemorySize, SMEM_GEMM);

    // 1. zero pad ring of g_xp
    ring_zero_kernel<<<(BB * 260 * 32 + 255) / 256, 256>>>();
    // 2. weight prep
    prep_weights_kernel<<<(4 * 16384 + 128 + 255) / 256, 256>>>(
        conv_w, in_proj_w, off_w, mask_w, off_b, mask_b, out_proj_w);
    // 3. NCHW -> NHWC transpose + pad
    {
        dim3 grid(BB * HH, WW / 32, CC / 32);
        transpose_pad_kernel<<<grid, dim3(32, 32)>>>(x);
    }
    // 4. fused GEMM1+GEMM2
    dual_gemm_kernel<<<NPIX / 256, 512, SMEM_GEMM>>>(
        p_bt + 0 * 16384, conv_b, p_bt + 1 * 16384, in_proj_b);
    // 5. depthwise + LN + GELU (4 px/warp, 3 CTAs/SM)
    dw_ln_gelu_kernel<<<BB * HH * 2, 256>>>(dw_w, dw_b, ln_g, ln_b);
    // 6. GEMM3: [offset|logits|pad] = d @ wcat + bcat (coalesced rows)
    mma_gemm_kernel<<<NPIX / 256, 512, SMEM_GEMM>>>(p_d, p_bt + 2 * 16384, p_bcat, p_om, 0);
    // 7. softmax + bilinear sampling (smem-windowed 8x8 tiles x group)
    sample_kernel<<<BB * 64 * GG, 512>>>();
    // 8. GEMM4: out = sampled @ out_proj_w + b, NCHW via smem transpose
    mma_gemm_kernel<<<NPIX / 256, 512, SMEM_GEMM>>>(p_sam, p_bt + 3 * 16384, out_proj_b, out, 2);
}